// round 6
// baseline (speedup 1.0000x reference)
#include <cuda_runtime.h>

// 2-layer LSTM: layer1 D=1 -> H=36, ReLU, layer2 36 -> 1. B=2048, T=2048, fp32.
// 256 blocks x 320 threads = 2 INDEPENDENT groups of 160 threads (5 warps).
// Each group owns 4 batches and its own named barrier -> groups drift freely.
//   group lanes wg 0..143 : layer1. (j=wg>>2, kq=wg&3); 9 k-steps x 4 gates
//     packed f32x2; quad reduce-scatter (xor2,xor1) -> lane owns batch kq.
//   group lanes wg 144..159 (warp 4 lanes 16..31): layer2 (4 gates x 4 ksegs).
// h duplicated {h,h}, row stride 12 floats (rows land on distinct banks).

#define TT   2048
#define H    36
#define HS   12
#define NT   320
#define GSZ  160
#define TCH  64

typedef unsigned long long u64;

__device__ __forceinline__ u64 pk2(float lo, float hi) {
    u64 r; asm("mov.b64 %0,{%1,%2};" : "=l"(r) : "f"(lo), "f"(hi)); return r;
}
__device__ __forceinline__ void upk2(u64 v, float& lo, float& hi) {
    asm("mov.b64 {%0,%1},%2;" : "=f"(lo), "=f"(hi) : "l"(v));
}
__device__ __forceinline__ u64 fma2(u64 a, u64 b, u64 c) {
    u64 d; asm("fma.rn.f32x2 %0,%1,%2,%3;" : "=l"(d) : "l"(a), "l"(b), "l"(c)); return d;
}
__device__ __forceinline__ u64 add2(u64 a, u64 b) {
    u64 d; asm("add.rn.f32x2 %0,%1,%2;" : "=l"(d) : "l"(a), "l"(b)); return d;
}
__device__ __forceinline__ u64 shfl64(unsigned m, u64 v, int lx) {
    return __shfl_xor_sync(m, v, lx);
}
__device__ __forceinline__ float tanhap(float x) {
    float y; asm("tanh.approx.f32 %0,%1;" : "=f"(y) : "f"(x)); return y;
}
__device__ __forceinline__ float sigap(float x) {
    return fmaf(0.5f, tanhap(0.5f * x), 0.5f);
}
__device__ __forceinline__ void gbar(int id) {
    asm volatile("bar.sync %0, %1;" :: "r"(id), "r"(GSZ) : "memory");
}

__global__ void __launch_bounds__(NT, 2) lstm2_kernel(
    const float* __restrict__ x,
    const float* __restrict__ Wih1, const float* __restrict__ Whh1,
    const float* __restrict__ bih1, const float* __restrict__ bhh1,
    const float* __restrict__ Wih2, const float* __restrict__ Whh2,
    const float* __restrict__ bih2, const float* __restrict__ bhh2,
    float* __restrict__ out)
{
    // per-group duplicated h: hsm[g][buf][unit][b*2+{0,1}] ; stride 12 floats
    __shared__ __align__(16) float hsm[2][2][H][HS];
    __shared__ float xsm[2][4][TCH];
    __shared__ float osm[2][4][TCH];

    const int tid   = threadIdx.x;
    const int g     = tid / GSZ;        // independent group 0/1
    const int wg    = tid % GSZ;
    const int barid = g + 1;            // named barriers 1 and 2
    const int bbase = blockIdx.x * 8 + g * 4;
    const bool isL1 = (wg < 144);
    const unsigned lmask = ((wg >> 5) == 4)
                         ? (isL1 ? 0x0000FFFFu : 0xFFFF0000u)
                         : 0xFFFFFFFFu;

    for (int i = tid; i < 2 * 2 * H * HS; i += NT) (&hsm[0][0][0][0])[i] = 0.0f;

    // ---- layer-1 identity + register weights ----
    int j = 0, kq = 0;
    u64 w1p[9][2];                   // packed {w_i,w_f},{w_g,w_o} per k
    u64 bias0 = 0, bias1 = 0;        // packed biases, only on kq==0 lanes
    float wx0=0, wx1=0, wx2=0, wx3=0;
    float c1 = 0.0f;
    if (isL1) {
        j = wg >> 2; kq = wg & 3;
        const int kb = kq * 9;
        #pragma unroll
        for (int kk = 0; kk < 9; ++kk) {
            const int k = kb + kk;
            w1p[kk][0] = pk2(Whh1[j * H + k],           Whh1[(H + j) * H + k]);
            w1p[kk][1] = pk2(Whh1[(2 * H + j) * H + k], Whh1[(3 * H + j) * H + k]);
        }
        wx0 = Wih1[j]; wx1 = Wih1[H + j]; wx2 = Wih1[2 * H + j]; wx3 = Wih1[3 * H + j];
        if (kq == 0) {
            bias0 = pk2(bih1[j] + bhh1[j],                 bih1[H + j] + bhh1[H + j]);
            bias1 = pk2(bih1[2 * H + j] + bhh1[2 * H + j], bih1[3 * H + j] + bhh1[3 * H + j]);
        }
    }

    // ---- layer-2 identity (group lanes 144..159) ----
    int g2 = 0, sg = 0, l2l = 0;
    float w2r[9]; float b2 = 0.0f, wh2g = 0.0f;
    float sA = 1.0f, sQ = 1.0f, sR = 0.0f;   // act(v) = sR + sQ*tanh(sA*v)
    float c2[4] = {0, 0, 0, 0}, h2[4] = {0, 0, 0, 0};
    if (!isL1) {
        l2l = wg - 144; g2 = l2l & 3; sg = l2l >> 2;
        #pragma unroll
        for (int s = 0; s < 9; ++s) w2r[s] = Wih2[g2 * H + sg * 9 + s];
        b2 = bih2[g2] + bhh2[g2];
        wh2g = Whh2[g2];
        if (g2 != 2) { sA = 0.5f; sQ = 0.5f; sR = 0.5f; }
    }
    __syncthreads();

    int cur = 0;
    for (int t = 0; t <= TT; ++t) {
        const int ti = t & (TCH - 1);
        if (ti == 0 && t < TT) {
            gbar(barid);
            for (int idx = wg; idx < 4 * TCH; idx += GSZ) {
                const int b = idx >> 6, i2 = idx & (TCH - 1);
                xsm[g][b][i2] = x[(bbase + b) * TT + t + i2];
            }
            gbar(barid);
        } else if (ti == 1 && t > TCH) {
            gbar(barid);
            const int tb = t - (TCH + 1);
            for (int idx = wg; idx < 4 * TCH; idx += GSZ) {
                const int b = idx >> 6, i2 = idx & (TCH - 1);
                out[(bbase + b) * TT + tb + i2] = osm[g][b][i2];
            }
            gbar(barid);
        }

        if (isL1 && t < TT) {
            // ---- matvec: 9 k-steps, 4 batches, packed gate pairs ----
            u64 a0[4], a1[4];
            a0[0] = bias0; a0[1] = bias0; a0[2] = bias0; a0[3] = bias0;
            a1[0] = bias1; a1[1] = bias1; a1[2] = bias1; a1[3] = bias1;
            const int kb = kq * 9;
            #pragma unroll
            for (int kk = 0; kk < 9; ++kk) {
                const ulonglong2 p01 = *(const ulonglong2*)&hsm[g][cur][kb + kk][0];
                const ulonglong2 p23 = *(const ulonglong2*)&hsm[g][cur][kb + kk][4];
                const u64 wA = w1p[kk][0], wB = w1p[kk][1];
                a0[0] = fma2(wA, p01.x, a0[0]); a1[0] = fma2(wB, p01.x, a1[0]);
                a0[1] = fma2(wA, p01.y, a0[1]); a1[1] = fma2(wB, p01.y, a1[1]);
                a0[2] = fma2(wA, p23.x, a0[2]); a1[2] = fma2(wB, p23.x, a1[2]);
                a0[3] = fma2(wA, p23.y, a0[3]); a1[3] = fma2(wB, p23.y, a1[3]);
            }
            // ---- quad reduce-scatter: round 1 over xor 2 ----
            const bool hi2 = (kq & 2) != 0;
            u64 s0 = hi2 ? a0[0] : a0[2];
            u64 s1 = hi2 ? a0[1] : a0[3];
            u64 s2 = hi2 ? a1[0] : a1[2];
            u64 s3 = hi2 ? a1[1] : a1[3];
            u64 k0 = hi2 ? a0[2] : a0[0];
            u64 k1 = hi2 ? a0[3] : a0[1];
            u64 k2 = hi2 ? a1[2] : a1[0];
            u64 k3 = hi2 ? a1[3] : a1[1];
            k0 = add2(k0, shfl64(lmask, s0, 2));
            k1 = add2(k1, shfl64(lmask, s1, 2));
            k2 = add2(k2, shfl64(lmask, s2, 2));
            k3 = add2(k3, shfl64(lmask, s3, 2));
            // ---- round 2 over xor 1: keep batch kq ----
            const bool hi1 = (kq & 1) != 0;
            u64 t0 = hi1 ? k0 : k1;
            u64 t1 = hi1 ? k2 : k3;
            u64 f0 = hi1 ? k1 : k0;   // {gate_i, gate_f} for batch kq
            u64 f1 = hi1 ? k3 : k2;   // {gate_g, gate_o}
            f0 = add2(f0, shfl64(lmask, t0, 1));
            f1 = add2(f1, shfl64(lmask, t1, 1));
            // ---- activations for batch bbase+kq ----
            float gi, gf, gg, go;
            upk2(f0, gi, gf);
            upk2(f1, gg, go);
            const float xb = xsm[g][kq][ti];
            gi = fmaf(wx0, xb, gi);
            gf = fmaf(wx1, xb, gf);
            gg = fmaf(wx2, xb, gg);
            go = fmaf(wx3, xb, go);
            const float cc = sigap(gf) * c1 + sigap(gi) * tanhap(gg);
            c1 = cc;
            const float hh = sigap(go) * tanhap(cc);
            *(float2*)&hsm[g][cur ^ 1][j][kq * 2] = make_float2(hh, hh);
        } else if (!isL1 && t >= 1) {
            // ---- layer 2 for time t-1 on lanes 16..31 of group warp 4 ----
            float4 p = make_float4(0.f, 0.f, 0.f, 0.f);
            #pragma unroll
            for (int s = 0; s < 9; ++s) {
                const float4 q01 = *(const float4*)&hsm[g][cur][sg * 9 + s][0];
                const float4 q23 = *(const float4*)&hsm[g][cur][sg * 9 + s][4];
                const float w = w2r[s];
                p.x = fmaf(w, fmaxf(q01.x, 0.f), p.x);
                p.y = fmaf(w, fmaxf(q01.z, 0.f), p.y);
                p.z = fmaf(w, fmaxf(q23.x, 0.f), p.z);
                p.w = fmaf(w, fmaxf(q23.z, 0.f), p.w);
            }
            #pragma unroll
            for (int off = 4; off <= 8; off <<= 1) {
                p.x += __shfl_xor_sync(0xFFFF0000u, p.x, off);
                p.y += __shfl_xor_sync(0xFFFF0000u, p.y, off);
                p.z += __shfl_xor_sync(0xFFFF0000u, p.z, off);
                p.w += __shfl_xor_sync(0xFFFF0000u, p.w, off);
            }
            float4 a;
            {
                const float v0 = p.x + fmaf(wh2g, h2[0], b2);
                const float v1 = p.y + fmaf(wh2g, h2[1], b2);
                const float v2 = p.z + fmaf(wh2g, h2[2], b2);
                const float v3 = p.w + fmaf(wh2g, h2[3], b2);
                a.x = fmaf(sQ, tanhap(sA * v0), sR);
                a.y = fmaf(sQ, tanhap(sA * v1), sR);
                a.z = fmaf(sQ, tanhap(sA * v2), sR);
                a.w = fmaf(sQ, tanhap(sA * v3), sR);
            }
            // gather gates from lanes 16+{0,1,2,3} (sg==0 copies)
            float4 Gi, Gf, Gg, Go;
            Gi.x = __shfl_sync(0xFFFF0000u, a.x, 16);
            Gi.y = __shfl_sync(0xFFFF0000u, a.y, 16);
            Gi.z = __shfl_sync(0xFFFF0000u, a.z, 16);
            Gi.w = __shfl_sync(0xFFFF0000u, a.w, 16);
            Gf.x = __shfl_sync(0xFFFF0000u, a.x, 17);
            Gf.y = __shfl_sync(0xFFFF0000u, a.y, 17);
            Gf.z = __shfl_sync(0xFFFF0000u, a.z, 17);
            Gf.w = __shfl_sync(0xFFFF0000u, a.w, 17);
            Gg.x = __shfl_sync(0xFFFF0000u, a.x, 18);
            Gg.y = __shfl_sync(0xFFFF0000u, a.y, 18);
            Gg.z = __shfl_sync(0xFFFF0000u, a.z, 18);
            Gg.w = __shfl_sync(0xFFFF0000u, a.w, 18);
            Go.x = __shfl_sync(0xFFFF0000u, a.x, 19);
            Go.y = __shfl_sync(0xFFFF0000u, a.y, 19);
            Go.z = __shfl_sync(0xFFFF0000u, a.z, 19);
            Go.w = __shfl_sync(0xFFFF0000u, a.w, 19);
            c2[0] = Gf.x * c2[0] + Gi.x * Gg.x;
            c2[1] = Gf.y * c2[1] + Gi.y * Gg.y;
            c2[2] = Gf.z * c2[2] + Gi.z * Gg.z;
            c2[3] = Gf.w * c2[3] + Gi.w * Gg.w;
            h2[0] = Go.x * tanhap(c2[0]);
            h2[1] = Go.y * tanhap(c2[1]);
            h2[2] = Go.z * tanhap(c2[2]);
            h2[3] = Go.w * tanhap(c2[3]);
            if (l2l == 0) {
                const int slot = (t - 1) & (TCH - 1);
                osm[g][0][slot] = h2[0];
                osm[g][1][slot] = h2[1];
                osm[g][2][slot] = h2[2];
                osm[g][3][slot] = h2[3];
            }
        }

        gbar(barid);
        cur ^= 1;
    }

    // ---- flush final chunk [TT-TCH, TT) (ordered by loop-end gbar) ----
    for (int idx = wg; idx < 4 * TCH; idx += GSZ) {
        const int b = idx >> 6, i2 = idx & (TCH - 1);
        out[(bbase + b) * TT + (TT - TCH) + i2] = osm[g][b][i2];
    }
}

extern "C" void kernel_launch(void* const* d_in, const int* in_sizes, int n_in,
                              void* d_out, int out_size) {
    (void)in_sizes; (void)n_in; (void)out_size;
    const float* x    = (const float*)d_in[0];
    const float* Wih1 = (const float*)d_in[1];
    const float* Whh1 = (const float*)d_in[2];
    const float* bih1 = (const float*)d_in[3];
    const float* bhh1 = (const float*)d_in[4];
    const float* Wih2 = (const float*)d_in[5];
    const float* Whh2 = (const float*)d_in[6];
    const float* bih2 = (const float*)d_in[7];
    const float* bhh2 = (const float*)d_in[8];
    float* out = (float*)d_out;

    lstm2_kernel<<<256, NT>>>(x, Wih1, Whh1, bih1, bhh1,
                              Wih2, Whh2, bih2, bhh2, out);
}

// round 8
// speedup vs baseline: 1.2122x; 1.2122x over previous
#include <cuda_runtime.h>

// 2-layer LSTM: layer1 D=1 -> H=36, ReLU, layer2 36 -> 1. B=2048, T=2048, fp32.
// 256 blocks x 192 threads, 8 batches/block:
//   tids 0..143 (warps 0..4, warp4 lanes 0..15): layer1. thread=(j=tid>>2,kq=tid&3).
//     Each owns 9 k-steps x 4 gates x ALL 8 batches: 16 packed-f32x2 accumulators,
//     144 FFMA2; h stored duplicated {h,h} so ulonglong2 LDS gives ready operands.
//     Quad reduce-scatter (xor2,xor1) -> lane kq owns batches {2kq, 2kq+1}.
//   tids 160..191 (warp 5): layer2. lane=(bh=l>>4, s4=(l>>2)&3, g2=l&3);
//     9 rows x 4 batches each, xor4/xor8 reduce, gather, pointwise.
// Activations: tanh.approx.f32 (sigmoid = 0.5*tanh(0.5x)+0.5).

#define TT   2048
#define H    36
#define HS   20     // dup row: 16 floats data + 4 pad (conflict-free)
#define BPB  8
#define NT   192
#define TCH  64

typedef unsigned long long u64;

__device__ __forceinline__ u64 pk2(float lo, float hi) {
    u64 r; asm("mov.b64 %0,{%1,%2};" : "=l"(r) : "f"(lo), "f"(hi)); return r;
}
__device__ __forceinline__ void upk2(u64 v, float& lo, float& hi) {
    asm("mov.b64 {%0,%1},%2;" : "=f"(lo), "=f"(hi) : "l"(v));
}
__device__ __forceinline__ u64 fma2(u64 a, u64 b, u64 c) {
    u64 d; asm("fma.rn.f32x2 %0,%1,%2,%3;" : "=l"(d) : "l"(a), "l"(b), "l"(c)); return d;
}
__device__ __forceinline__ u64 add2(u64 a, u64 b) {
    u64 d; asm("add.rn.f32x2 %0,%1,%2;" : "=l"(d) : "l"(a), "l"(b)); return d;
}
__device__ __forceinline__ u64 shfl64(unsigned m, u64 v, int lx) {
    return __shfl_xor_sync(m, v, lx);
}
__device__ __forceinline__ float tanhap(float x) {
    float y; asm("tanh.approx.f32 %0,%1;" : "=f"(y) : "f"(x)); return y;
}
__device__ __forceinline__ float sigap(float x) {
    return fmaf(0.5f, tanhap(0.5f * x), 0.5f);
}

__global__ void __launch_bounds__(NT, 2) lstm2_kernel(
    const float* __restrict__ x,
    const float* __restrict__ Wih1, const float* __restrict__ Whh1,
    const float* __restrict__ bih1, const float* __restrict__ bhh1,
    const float* __restrict__ Wih2, const float* __restrict__ Whh2,
    const float* __restrict__ bih2, const float* __restrict__ bhh2,
    float* __restrict__ out)
{
    // duplicated h: hsm[buf][unit][2b+{0,1}] = h(batch b), b in 0..7
    __shared__ __align__(16) float hsm[2][H][HS];
    __shared__ float xsm[BPB][TCH];
    __shared__ float osm[BPB][TCH];

    const int tid   = threadIdx.x;
    const int bbase = blockIdx.x * BPB;
    const bool isL1 = (tid < 144);
    const bool isL2 = (tid >= 160);
    const unsigned lmask = ((tid >> 5) == 4) ? 0x0000FFFFu : 0xFFFFFFFFu;

    for (int i = tid; i < 2 * H * HS; i += NT) (&hsm[0][0][0])[i] = 0.0f;

    // ---- layer-1 identity + register weights ----
    int j = 0, kq = 0;
    u64 w1p[9][2];                   // packed {w_i,w_f},{w_g,w_o} per k
    u64 bias0 = 0, bias1 = 0;        // packed biases, only on kq==0 lanes
    float wx0=0, wx1=0, wx2=0, wx3=0;
    float c1a = 0.0f, c1b = 0.0f;
    if (isL1) {
        j = tid >> 2; kq = tid & 3;
        const int kb = kq * 9;
        #pragma unroll
        for (int kk = 0; kk < 9; ++kk) {
            const int k = kb + kk;
            w1p[kk][0] = pk2(Whh1[j * H + k],           Whh1[(H + j) * H + k]);
            w1p[kk][1] = pk2(Whh1[(2 * H + j) * H + k], Whh1[(3 * H + j) * H + k]);
        }
        wx0 = Wih1[j]; wx1 = Wih1[H + j]; wx2 = Wih1[2 * H + j]; wx3 = Wih1[3 * H + j];
        if (kq == 0) {
            bias0 = pk2(bih1[j] + bhh1[j],                 bih1[H + j] + bhh1[H + j]);
            bias1 = pk2(bih1[2 * H + j] + bhh1[2 * H + j], bih1[3 * H + j] + bhh1[3 * H + j]);
        }
    }

    // ---- layer-2 identity (warp 5): bh = batch half, s4 = k-seg, g2 = gate ----
    int bh = 0, g2 = 0, s4 = 0, l2l = 0;
    float w2r[9]; float b2 = 0.0f, wh2g = 0.0f;
    float sA = 1.0f, sQ = 1.0f, sR = 0.0f;   // act(v) = sR + sQ*tanh(sA*v)
    float c2[4] = {0, 0, 0, 0}, h2[4] = {0, 0, 0, 0};
    if (isL2) {
        l2l = tid - 160; bh = l2l >> 4; s4 = (l2l >> 2) & 3; g2 = l2l & 3;
        #pragma unroll
        for (int s = 0; s < 9; ++s) w2r[s] = Wih2[g2 * H + s4 * 9 + s];
        b2 = (s4 == 0) ? (bih2[g2] + bhh2[g2]) : 0.0f;   // bias once per reduced sum
        wh2g = Whh2[g2];
        if (g2 != 2) { sA = 0.5f; sQ = 0.5f; sR = 0.5f; }
    }
    __syncthreads();

    int cur = 0;
    for (int t = 0; t <= TT; ++t) {
        const int ti = t & (TCH - 1);
        if (ti == 0 && t < TT) {
            __syncthreads();
            for (int idx = tid; idx < BPB * TCH; idx += NT) {
                const int b = idx >> 6, i2 = idx & (TCH - 1);
                xsm[b][i2] = x[(bbase + b) * TT + t + i2];
            }
            __syncthreads();
        } else if (ti == 1 && t > TCH) {
            __syncthreads();
            const int tb = t - (TCH + 1);
            for (int idx = tid; idx < BPB * TCH; idx += NT) {
                const int b = idx >> 6, i2 = idx & (TCH - 1);
                out[(bbase + b) * TT + tb + i2] = osm[b][i2];
            }
            __syncthreads();
        }

        if (isL1 && t < TT) {
            // ---- matvec: 9 k-steps x 4 gates x 8 batches, packed gate pairs ----
            u64 a0[8], a1[8];
            #pragma unroll
            for (int b = 0; b < 8; ++b) { a0[b] = bias0; a1[b] = bias1; }
            const int kb = kq * 9;
            #pragma unroll
            for (int kk = 0; kk < 9; ++kk) {
                const ulonglong2 p0 = *(const ulonglong2*)&hsm[cur][kb + kk][0];
                const ulonglong2 p1 = *(const ulonglong2*)&hsm[cur][kb + kk][4];
                const ulonglong2 p2 = *(const ulonglong2*)&hsm[cur][kb + kk][8];
                const ulonglong2 p3 = *(const ulonglong2*)&hsm[cur][kb + kk][12];
                const u64 wA = w1p[kk][0], wB = w1p[kk][1];
                a0[0] = fma2(wA, p0.x, a0[0]); a1[0] = fma2(wB, p0.x, a1[0]);
                a0[1] = fma2(wA, p0.y, a0[1]); a1[1] = fma2(wB, p0.y, a1[1]);
                a0[2] = fma2(wA, p1.x, a0[2]); a1[2] = fma2(wB, p1.x, a1[2]);
                a0[3] = fma2(wA, p1.y, a0[3]); a1[3] = fma2(wB, p1.y, a1[3]);
                a0[4] = fma2(wA, p2.x, a0[4]); a1[4] = fma2(wB, p2.x, a1[4]);
                a0[5] = fma2(wA, p2.y, a0[5]); a1[5] = fma2(wB, p2.y, a1[5]);
                a0[6] = fma2(wA, p3.x, a0[6]); a1[6] = fma2(wB, p3.x, a1[6]);
                a0[7] = fma2(wA, p3.y, a0[7]); a1[7] = fma2(wB, p3.y, a1[7]);
            }
            // ---- quad reduce-scatter. round 1 (xor 2): keep a batch-half ----
            const bool hi2 = (kq & 2) != 0;
            u64 kA0 = hi2 ? a0[4] : a0[0];  u64 sA0 = hi2 ? a0[0] : a0[4];
            u64 kA1 = hi2 ? a0[5] : a0[1];  u64 sA1 = hi2 ? a0[1] : a0[5];
            u64 kA2 = hi2 ? a0[6] : a0[2];  u64 sA2 = hi2 ? a0[2] : a0[6];
            u64 kA3 = hi2 ? a0[7] : a0[3];  u64 sA3 = hi2 ? a0[3] : a0[7];
            u64 kB0 = hi2 ? a1[4] : a1[0];  u64 sB0 = hi2 ? a1[0] : a1[4];
            u64 kB1 = hi2 ? a1[5] : a1[1];  u64 sB1 = hi2 ? a1[1] : a1[5];
            u64 kB2 = hi2 ? a1[6] : a1[2];  u64 sB2 = hi2 ? a1[2] : a1[6];
            u64 kB3 = hi2 ? a1[7] : a1[3];  u64 sB3 = hi2 ? a1[3] : a1[7];
            kA0 = add2(kA0, shfl64(lmask, sA0, 2));
            kA1 = add2(kA1, shfl64(lmask, sA1, 2));
            kA2 = add2(kA2, shfl64(lmask, sA2, 2));
            kA3 = add2(kA3, shfl64(lmask, sA3, 2));
            kB0 = add2(kB0, shfl64(lmask, sB0, 2));
            kB1 = add2(kB1, shfl64(lmask, sB1, 2));
            kB2 = add2(kB2, shfl64(lmask, sB2, 2));
            kB3 = add2(kB3, shfl64(lmask, sB3, 2));
            // ---- round 2 (xor 1): keep batches {2kq, 2kq+1} ----
            const bool hi1 = (kq & 1) != 0;
            u64 f0 = hi1 ? kA2 : kA0;   u64 t0 = hi1 ? kA0 : kA2;
            u64 f1 = hi1 ? kA3 : kA1;   u64 t1 = hi1 ? kA1 : kA3;
            u64 f2 = hi1 ? kB2 : kB0;   u64 t2 = hi1 ? kB0 : kB2;
            u64 f3 = hi1 ? kB3 : kB1;   u64 t3 = hi1 ? kB1 : kB3;
            f0 = add2(f0, shfl64(lmask, t0, 1));
            f1 = add2(f1, shfl64(lmask, t1, 1));
            f2 = add2(f2, shfl64(lmask, t2, 1));
            f3 = add2(f3, shfl64(lmask, t3, 1));
            // ---- activations for batches 2kq, 2kq+1 ----
            float gi0, gf0, gg0, go0, gi1, gf1, gg1, go1;
            upk2(f0, gi0, gf0);
            upk2(f1, gi1, gf1);
            upk2(f2, gg0, go0);
            upk2(f3, gg1, go1);
            const float xb0 = xsm[2 * kq][ti];
            const float xb1 = xsm[2 * kq + 1][ti];
            gi0 = fmaf(wx0, xb0, gi0); gi1 = fmaf(wx0, xb1, gi1);
            gf0 = fmaf(wx1, xb0, gf0); gf1 = fmaf(wx1, xb1, gf1);
            gg0 = fmaf(wx2, xb0, gg0); gg1 = fmaf(wx2, xb1, gg1);
            go0 = fmaf(wx3, xb0, go0); go1 = fmaf(wx3, xb1, go1);
            const float cc0 = sigap(gf0) * c1a + sigap(gi0) * tanhap(gg0);
            const float cc1 = sigap(gf1) * c1b + sigap(gi1) * tanhap(gg1);
            c1a = cc0; c1b = cc1;
            const float hh0 = sigap(go0) * tanhap(cc0);
            const float hh1 = sigap(go1) * tanhap(cc1);
            // duplicated store for batches 2kq, 2kq+1
            *(float4*)&hsm[cur ^ 1][j][kq * 4] = make_float4(hh0, hh0, hh1, hh1);
        } else if (isL2 && t >= 1) {
            // ---- layer 2 for time t-1: 9 rows x 4 batches (bh half) ----
            float p0 = b2, p1 = b2, p2 = b2, p3 = b2;
            #pragma unroll
            for (int s = 0; s < 9; ++s) {
                const int row = s4 * 9 + s;
                const float4 q0 = *(const float4*)&hsm[cur][row][bh * 8];
                const float4 q1 = *(const float4*)&hsm[cur][row][bh * 8 + 4];
                const float w = w2r[s];
                p0 = fmaf(w, fmaxf(q0.x, 0.f), p0);
                p1 = fmaf(w, fmaxf(q0.z, 0.f), p1);
                p2 = fmaf(w, fmaxf(q1.x, 0.f), p2);
                p3 = fmaf(w, fmaxf(q1.z, 0.f), p3);
            }
            // reduce over 4 k-segments (xor 4, xor 8)
            #pragma unroll
            for (int off = 4; off <= 8; off <<= 1) {
                p0 += __shfl_xor_sync(0xFFFFFFFFu, p0, off);
                p1 += __shfl_xor_sync(0xFFFFFFFFu, p1, off);
                p2 += __shfl_xor_sync(0xFFFFFFFFu, p2, off);
                p3 += __shfl_xor_sync(0xFFFFFFFFu, p3, off);
            }
            // recurrent + activation (branchless per-gate)
            float a0v = fmaf(sQ, tanhap(sA * (p0 + wh2g * h2[0])), sR);
            float a1v = fmaf(sQ, tanhap(sA * (p1 + wh2g * h2[1])), sR);
            float a2v = fmaf(sQ, tanhap(sA * (p2 + wh2g * h2[2])), sR);
            float a3v = fmaf(sQ, tanhap(sA * (p3 + wh2g * h2[3])), sR);
            // gather the 4 gates from lanes (l & ~3) | g  (same s4 group, valid copies)
            const int gb = l2l & ~3;
            float Gi0 = __shfl_sync(0xFFFFFFFFu, a0v, gb + 0);
            float Gi1 = __shfl_sync(0xFFFFFFFFu, a1v, gb + 0);
            float Gi2 = __shfl_sync(0xFFFFFFFFu, a2v, gb + 0);
            float Gi3 = __shfl_sync(0xFFFFFFFFu, a3v, gb + 0);
            float Gf0 = __shfl_sync(0xFFFFFFFFu, a0v, gb + 1);
            float Gf1 = __shfl_sync(0xFFFFFFFFu, a1v, gb + 1);
            float Gf2 = __shfl_sync(0xFFFFFFFFu, a2v, gb + 1);
            float Gf3 = __shfl_sync(0xFFFFFFFFu, a3v, gb + 1);
            float Gg0 = __shfl_sync(0xFFFFFFFFu, a0v, gb + 2);
            float Gg1 = __shfl_sync(0xFFFFFFFFu, a1v, gb + 2);
            float Gg2 = __shfl_sync(0xFFFFFFFFu, a2v, gb + 2);
            float Gg3 = __shfl_sync(0xFFFFFFFFu, a3v, gb + 2);
            float Go0 = __shfl_sync(0xFFFFFFFFu, a0v, gb + 3);
            float Go1 = __shfl_sync(0xFFFFFFFFu, a1v, gb + 3);
            float Go2 = __shfl_sync(0xFFFFFFFFu, a2v, gb + 3);
            float Go3 = __shfl_sync(0xFFFFFFFFu, a3v, gb + 3);
            c2[0] = Gf0 * c2[0] + Gi0 * Gg0;
            c2[1] = Gf1 * c2[1] + Gi1 * Gg1;
            c2[2] = Gf2 * c2[2] + Gi2 * Gg2;
            c2[3] = Gf3 * c2[3] + Gi3 * Gg3;
            h2[0] = Go0 * tanhap(c2[0]);
            h2[1] = Go1 * tanhap(c2[1]);
            h2[2] = Go2 * tanhap(c2[2]);
            h2[3] = Go3 * tanhap(c2[3]);
            if ((l2l & 15) == 0) {
                const int slot = (t - 1) & (TCH - 1);
                osm[bh * 4 + 0][slot] = h2[0];
                osm[bh * 4 + 1][slot] = h2[1];
                osm[bh * 4 + 2][slot] = h2[2];
                osm[bh * 4 + 3][slot] = h2[3];
            }
        }

        __syncthreads();
        cur ^= 1;
    }

    // ---- flush final chunk [TT-TCH, TT) ----
    for (int idx = tid; idx < BPB * TCH; idx += NT) {
        const int b = idx >> 6, i2 = idx & (TCH - 1);
        out[(bbase + b) * TT + (TT - TCH) + i2] = osm[b][i2];
    }
}

extern "C" void kernel_launch(void* const* d_in, const int* in_sizes, int n_in,
                              void* d_out, int out_size) {
    (void)in_sizes; (void)n_in; (void)out_size;
    const float* x    = (const float*)d_in[0];
    const float* Wih1 = (const float*)d_in[1];
    const float* Whh1 = (const float*)d_in[2];
    const float* bih1 = (const float*)d_in[3];
    const float* bhh1 = (const float*)d_in[4];
    const float* Wih2 = (const float*)d_in[5];
    const float* Whh2 = (const float*)d_in[6];
    const float* bih2 = (const float*)d_in[7];
    const float* bhh2 = (const float*)d_in[8];
    float* out = (float*)d_out;

    lstm2_kernel<<<256, NT>>>(x, Wih1, Whh1, bih1, bhh1,
                              Wih2, Whh2, bih2, bhh2, out);
}